// round 4
// baseline (speedup 1.0000x reference)
#include <cuda_runtime.h>

#define NN 50000
#define EE 800000
#define DD 64
#define HH 4
#define OUTD 64

// Scratch (allocation-free: __device__ globals)
__device__ float g_deg[NN];
__device__ float g_nd[NN];
__device__ float g_a[NN * HH];           // h[v] . w1_h
__device__ float g_bp[NN * HH];          // h[v] . w2_h
__device__ float g_q[NN * HH * OUTD];    // nd[v] * (h[v] @ W_cat[:, h*D:(h+1)*D]^T)
__device__ float g_agg[NN * OUTD];       // per-target-node accumulated projected messages

// ---------------------------------------------------------------------------
// K0: zero scratch that is accumulated into (graph replays require re-zero)
// ---------------------------------------------------------------------------
__global__ void k_zero() {
    int i = blockIdx.x * blockDim.x + threadIdx.x;
    if (i < NN * OUTD) g_agg[i] = 0.0f;
    if (i < NN) g_deg[i] = 0.0f;
}

// ---------------------------------------------------------------------------
// K1: out-degree count over row
// ---------------------------------------------------------------------------
__global__ void k_deg(const int* __restrict__ ei) {
    int e = blockIdx.x * blockDim.x + threadIdx.x;
    if (e < EE) atomicAdd(&g_deg[ei[e]], 1.0f);
}

// ---------------------------------------------------------------------------
// K2: per-node precompute: nd, gate projections a/bp, projected q
//     block = 256 threads, 8 nodes per block
// ---------------------------------------------------------------------------
__global__ void k_node(const float* __restrict__ h,
                       const float* __restrict__ gate_w,
                       const float* __restrict__ W_cat) {
    __shared__ float hs[8][64];
    __shared__ float nds[8];
    const int v0 = blockIdx.x * 8;
    const int t = threadIdx.x;

    // cooperative load of 8 node feature rows
    #pragma unroll
    for (int i = t; i < 8 * 64; i += 256) {
        int v = i >> 6, d = i & 63;
        int vg = v0 + v;
        hs[v][d] = (vg < NN) ? h[vg * 64 + d] : 0.0f;
    }
    __syncthreads();

    if (t < 8) {
        int vg = v0 + t;
        float ndv = 0.0f;
        if (vg < NN) {
            float dg = g_deg[vg];
            ndv = rsqrtf(fmaxf(dg, 1.0f));
            g_nd[vg] = ndv;
        }
        nds[t] = ndv;
    }
    // gate projections: 64 threads, each one (node v, k) pair; k: h = k&3, part = k>>2
    if (t >= 64 && t < 128) {
        int i = t - 64;
        int v = i >> 3, k = i & 7;
        int hh = k & 3, part = k >> 2;
        int vg = v0 + v;
        if (vg < NN) {
            const float* w = gate_w + hh * 128 + part * 64;
            float acc = 0.0f;
            #pragma unroll
            for (int d = 0; d < 64; d++) acc += hs[v][d] * w[d];
            if (part == 0) g_a[vg * 4 + hh] = acc;
            else           g_bp[vg * 4 + hh] = acc;
        }
    }
    __syncthreads();

    // q: thread t owns column j = t (h = j>>6, o = j&63) for all 8 nodes
    const int hh = t >> 6, o = t & 63;
    const float4* Wrow = reinterpret_cast<const float4*>(W_cat + o * 256 + hh * 64);
    float acc[8];
    #pragma unroll
    for (int v = 0; v < 8; v++) acc[v] = 0.0f;
    #pragma unroll
    for (int dq = 0; dq < 16; dq++) {
        float4 w = Wrow[dq];
        #pragma unroll
        for (int v = 0; v < 8; v++) {
            float4 hv = reinterpret_cast<const float4*>(hs[v])[dq];
            acc[v] += w.x * hv.x + w.y * hv.y + w.z * hv.z + w.w * hv.w;
        }
    }
    #pragma unroll
    for (int v = 0; v < 8; v++) {
        int vg = v0 + v;
        if (vg < NN) g_q[vg * 256 + t] = nds[v] * acc[v];
    }
}

// ---------------------------------------------------------------------------
// K3: edge kernel — one warp per edge.
//     gates via 4 scalar gathers + shfl; 64-float projected message RED'd
//     into agg[col].
// ---------------------------------------------------------------------------
__global__ void k_edge(const int* __restrict__ ei,
                       const float* __restrict__ gate_b) {
    const int warpId = (blockIdx.x * blockDim.x + threadIdx.x) >> 5;
    const int lane = threadIdx.x & 31;
    if (warpId >= EE) return;

    const int row = ei[warpId];
    const int col = ei[EE + warpId];

    float gv = 0.0f;
    if (lane < 4) {
        gv = tanhf(g_a[row * 4 + lane] + g_bp[col * 4 + lane] + gate_b[lane]);
    }
    const unsigned FULL = 0xffffffffu;
    const float g0 = __shfl_sync(FULL, gv, 0);
    const float g1 = __shfl_sync(FULL, gv, 1);
    const float g2 = __shfl_sync(FULL, gv, 2);
    const float g3 = __shfl_sync(FULL, gv, 3);

    const float* __restrict__ qr = g_q + row * 256;
    float m0 = g0 * qr[lane]        + g1 * qr[64 + lane]
             + g2 * qr[128 + lane]  + g3 * qr[192 + lane];
    float m1 = g0 * qr[32 + lane]   + g1 * qr[96 + lane]
             + g2 * qr[160 + lane]  + g3 * qr[224 + lane];

    float* ag = g_agg + col * 64;
    atomicAdd(&ag[lane], m0);
    atomicAdd(&ag[32 + lane], m1);
}

// ---------------------------------------------------------------------------
// K4: output: relu(nd[n] * agg[n, :] + b_cat)
// ---------------------------------------------------------------------------
__global__ void k_out(const float* __restrict__ b_cat,
                      float* __restrict__ out) {
    int i = blockIdx.x * blockDim.x + threadIdx.x;
    if (i >= NN * OUTD) return;
    int n = i >> 6, o = i & 63;
    float v = g_nd[n] * g_agg[i] + b_cat[o];
    out[i] = fmaxf(v, 0.0f);
}

extern "C" void kernel_launch(void* const* d_in, const int* in_sizes, int n_in,
                              void* d_out, int out_size) {
    const float* h      = (const float*)d_in[0];
    const int*   ei     = (const int*)d_in[1];
    const float* gate_w = (const float*)d_in[2];
    const float* gate_b = (const float*)d_in[3];
    const float* W_cat  = (const float*)d_in[4];
    const float* b_cat  = (const float*)d_in[5];
    float* out = (float*)d_out;

    k_zero<<<(NN * OUTD + 255) / 256, 256>>>();
    k_deg<<<(EE + 255) / 256, 256>>>(ei);
    k_node<<<(NN + 7) / 8, 256>>>(h, gate_w, W_cat);
    k_edge<<<(EE * 32 + 255) / 256, 256>>>(ei, gate_b);
    k_out<<<(NN * OUTD + 255) / 256, 256>>>(b_cat, out);
}

// round 5
// speedup vs baseline: 1.3541x; 1.3541x over previous
#include <cuda_runtime.h>

#define NN 50000
#define EE 800000
#define DD 64
#define HH 4
#define OUTD 64

// ---------------------------------------------------------------------------
// Scratch (__device__ globals: allocation-free)
// ---------------------------------------------------------------------------
__device__ int   g_degi[NN];        // out-degree over row (for nd)
__device__ int   g_cnt[NN];         // in-degree over col (for CSR)
__device__ int   g_off[NN + 1];     // CSR offsets by col
__device__ int   g_cursor[NN];      // scatter cursors
__device__ int   g_srow[EE];        // row index of edges, sorted by col
__device__ float g_nd[NN];
__device__ float g_a[NN * HH];      // h[v] . w1_h
__device__ float g_bp[NN * HH];     // h[v] . w2_h
__device__ float g_hn[NN * DD];     // nd[v] * h[v]
__device__ float g_s[NN * HH * DD]; // aggregated (pre-projection) messages

// ---------------------------------------------------------------------------
// K0: zero counters
// ---------------------------------------------------------------------------
__global__ void k_init() {
    int i = blockIdx.x * blockDim.x + threadIdx.x;
    if (i < NN) { g_degi[i] = 0; g_cnt[i] = 0; }
}

// ---------------------------------------------------------------------------
// K1: degree counts (row for nd, col for CSR)
// ---------------------------------------------------------------------------
__global__ void k_count(const int* __restrict__ ei) {
    int e = blockIdx.x * blockDim.x + threadIdx.x;
    if (e < EE) {
        atomicAdd(&g_degi[ei[e]], 1);
        atomicAdd(&g_cnt[ei[EE + e]], 1);
    }
}

// ---------------------------------------------------------------------------
// K2: single-block exclusive scan of g_cnt -> g_off, g_cursor
// ---------------------------------------------------------------------------
__global__ void k_scan() {
    __shared__ int wsum[32];
    const int t = threadIdx.x, lane = t & 31, wid = t >> 5;
    int running = 0;
    for (int base = 0; base < NN; base += 1024) {
        int i = base + t;
        int v = (i < NN) ? g_cnt[i] : 0;
        int x = v;
        #pragma unroll
        for (int d = 1; d < 32; d <<= 1) {
            int y = __shfl_up_sync(0xffffffffu, x, d);
            if (lane >= d) x += y;
        }
        if (lane == 31) wsum[wid] = x;
        __syncthreads();
        if (wid == 0) {
            int w = wsum[lane];
            #pragma unroll
            for (int d = 1; d < 32; d <<= 1) {
                int y = __shfl_up_sync(0xffffffffu, w, d);
                if (lane >= d) w += y;
            }
            wsum[lane] = w;
        }
        __syncthreads();
        int woff = (wid > 0) ? wsum[wid - 1] : 0;
        int excl = running + woff + x - v;
        if (i < NN) { g_off[i] = excl; g_cursor[i] = excl; }
        running += wsum[31];
        __syncthreads();
    }
    if (t == 0) g_off[NN] = running;
}

// ---------------------------------------------------------------------------
// K3: per-node precompute: nd, hn = nd*h, gate projections a/bp
//     one warp per node
// ---------------------------------------------------------------------------
__global__ void k_node(const float* __restrict__ h,
                       const float* __restrict__ gate_w) {
    const int t = threadIdx.x, lane = t & 31;
    const int n = blockIdx.x * 8 + (t >> 5);
    if (n >= NN) return;

    float2 h2 = *reinterpret_cast<const float2*>(h + n * 64 + 2 * lane);
    float ndv = rsqrtf(fmaxf((float)g_degi[n], 1.0f));
    if (lane == 0) g_nd[n] = ndv;
    float2 hn2 = make_float2(ndv * h2.x, ndv * h2.y);
    *reinterpret_cast<float2*>(g_hn + n * 64 + 2 * lane) = hn2;

    #pragma unroll
    for (int hh = 0; hh < 4; hh++) {
        const float* w = gate_w + hh * 128;
        float p1 = h2.x * w[2 * lane] + h2.y * w[2 * lane + 1];
        float p2 = h2.x * w[64 + 2 * lane] + h2.y * w[64 + 2 * lane + 1];
        #pragma unroll
        for (int d = 16; d; d >>= 1) {
            p1 += __shfl_xor_sync(0xffffffffu, p1, d);
            p2 += __shfl_xor_sync(0xffffffffu, p2, d);
        }
        if (lane == 0) { g_a[n * 4 + hh] = p1; g_bp[n * 4 + hh] = p2; }
    }
}

// ---------------------------------------------------------------------------
// K4: scatter edges into col-sorted order (store row index)
// ---------------------------------------------------------------------------
__global__ void k_scatter(const int* __restrict__ ei) {
    int e = blockIdx.x * blockDim.x + threadIdx.x;
    if (e < EE) {
        int row = ei[e];
        int col = ei[EE + e];
        int pos = atomicAdd(&g_cursor[col], 1);
        g_srow[pos] = row;
    }
}

// ---------------------------------------------------------------------------
// K5: segment reduction, one warp per destination node, no atomics.
//     Per 8-edge batch: lanes compute 32 gates (8 edges x 4 heads), then
//     each edge's hn[row] (float2/lane) is FMA'd into 8 register slots.
//     Writes s[col][h][d] scaled by nd[col].
// ---------------------------------------------------------------------------
__global__ void k_gather(const float* __restrict__ gate_b) {
    const int t = threadIdx.x, lane = t & 31;
    const int n = blockIdx.x * 8 + (t >> 5);
    if (n >= NN) return;

    const int beg = g_off[n], end = g_off[n + 1];
    const float ndc = g_nd[n];
    const int hh = lane & 3;
    const float bp_h = g_bp[n * 4 + hh];
    const float b_h = gate_b[hh];

    float acc[8];
    #pragma unroll
    for (int i = 0; i < 8; i++) acc[i] = 0.0f;

    for (int base = beg; base < end; base += 8) {
        int idx = base + (lane >> 2);
        int row_l = (idx < end) ? g_srow[idx] : 0;
        float g = tanhf(g_a[row_l * 4 + hh] + bp_h + b_h);
        int cnt = end - base;   // warp-uniform
        #pragma unroll
        for (int j = 0; j < 8; j++) {
            if (j < cnt) {
                int   rj = __shfl_sync(0xffffffffu, row_l, j * 4);
                float g0 = __shfl_sync(0xffffffffu, g, j * 4 + 0);
                float g1 = __shfl_sync(0xffffffffu, g, j * 4 + 1);
                float g2 = __shfl_sync(0xffffffffu, g, j * 4 + 2);
                float g3 = __shfl_sync(0xffffffffu, g, j * 4 + 3);
                float2 hv = *reinterpret_cast<const float2*>(g_hn + rj * 64 + 2 * lane);
                acc[0] += g0 * hv.x; acc[1] += g0 * hv.y;
                acc[2] += g1 * hv.x; acc[3] += g1 * hv.y;
                acc[4] += g2 * hv.x; acc[5] += g2 * hv.y;
                acc[6] += g3 * hv.x; acc[7] += g3 * hv.y;
            }
        }
    }

    float* sp = g_s + n * 256;
    #pragma unroll
    for (int k = 0; k < 4; k++) {
        float2 v = make_float2(ndc * acc[k * 2], ndc * acc[k * 2 + 1]);
        *reinterpret_cast<float2*>(sp + k * 64 + 2 * lane) = v;
    }
}

// ---------------------------------------------------------------------------
// K6: out = relu(s @ W_cat^T + b_cat)
//     block: 256 threads, 16 nodes; thread = (o = t&63, k-quarter = t>>6)
//     W quarter-row kept in registers; s tile staged in smem (broadcast LDS)
// ---------------------------------------------------------------------------
__global__ __launch_bounds__(256) void k_proj(const float* __restrict__ W_cat,
                                              const float* __restrict__ b_cat,
                                              float* __restrict__ out) {
    __shared__ float s_sh[16][256];
    __shared__ float red[3][16][64];
    const int t = threadIdx.x;
    const int v0 = blockIdx.x * 16;

    const float4* sg = reinterpret_cast<const float4*>(g_s + v0 * 256);
    float4* ss4 = reinterpret_cast<float4*>(&s_sh[0][0]);
    #pragma unroll
    for (int i = 0; i < 4; i++) ss4[t + i * 256] = sg[t + i * 256];
    __syncthreads();

    const int o = t & 63, qr = t >> 6;
    const float4* wg = reinterpret_cast<const float4*>(W_cat + o * 256 + qr * 64);
    float4 wr[16];
    #pragma unroll
    for (int i = 0; i < 16; i++) wr[i] = wg[i];

    float acc[16];
    #pragma unroll
    for (int v = 0; v < 16; v++) acc[v] = 0.0f;

    #pragma unroll
    for (int kk = 0; kk < 16; kk++) {
        float4 w4 = wr[kk];
        #pragma unroll
        for (int v = 0; v < 16; v++) {
            float4 sv = *reinterpret_cast<const float4*>(&s_sh[v][qr * 64 + kk * 4]);
            acc[v] += w4.x * sv.x + w4.y * sv.y + w4.z * sv.z + w4.w * sv.w;
        }
    }

    if (qr > 0) {
        #pragma unroll
        for (int v = 0; v < 16; v++) red[qr - 1][v][o] = acc[v];
    }
    __syncthreads();
    if (qr == 0) {
        float b = b_cat[o];
        #pragma unroll
        for (int v = 0; v < 16; v++) {
            float sum = acc[v] + red[0][v][o] + red[1][v][o] + red[2][v][o] + b;
            out[(v0 + v) * 64 + o] = fmaxf(sum, 0.0f);
        }
    }
}

// ---------------------------------------------------------------------------
extern "C" void kernel_launch(void* const* d_in, const int* in_sizes, int n_in,
                              void* d_out, int out_size) {
    const float* h      = (const float*)d_in[0];
    const int*   ei     = (const int*)d_in[1];
    const float* gate_w = (const float*)d_in[2];
    const float* gate_b = (const float*)d_in[3];
    const float* W_cat  = (const float*)d_in[4];
    const float* b_cat  = (const float*)d_in[5];
    float* out = (float*)d_out;

    k_init<<<(NN + 255) / 256, 256>>>();
    k_count<<<(EE + 255) / 256, 256>>>(ei);
    k_scan<<<1, 1024>>>();
    k_node<<<(NN + 7) / 8, 256>>>(h, gate_w);
    k_scatter<<<(EE + 255) / 256, 256>>>(ei);
    k_gather<<<(NN + 7) / 8, 256>>>(gate_b);
    k_proj<<<NN / 16, 256>>>(W_cat, b_cat, out);
}

// round 7
// speedup vs baseline: 1.4713x; 1.0866x over previous
#include <cuda_runtime.h>

#define NN 50000
#define EE 800000
#define DD 64
#define HH 4
#define OUTD 64

// ---------------------------------------------------------------------------
// Scratch (__device__ globals: allocation-free)
// ---------------------------------------------------------------------------
__device__ int   g_degi[NN];        // out-degree over row (for nd)
__device__ int   g_cnt[NN];         // in-degree over col (for CSR)
__device__ int   g_off[NN + 1];     // CSR offsets by col
__device__ int   g_cursor[NN];      // scatter cursors
__device__ int   g_srow[EE];        // row index of edges, sorted by col
__device__ float g_nd[NN];
__device__ float g_a[NN * HH];      // h[v] . w1_h
__device__ float g_bp[NN * HH];     // h[v] . w2_h
__device__ float g_hn[NN * DD];     // nd[v] * h[v]
__device__ float g_s[NN * HH * DD]; // aggregated (pre-projection) messages
__device__ int   g_bsum[256];       // scan block sums
__device__ int   g_bpre[256];       // scan block prefixes

// ---------------------------------------------------------------------------
// packed f32x2 helpers (FFMA2)
// ---------------------------------------------------------------------------
__device__ __forceinline__ unsigned long long pack2(float a, float b) {
    unsigned long long r;
    asm("mov.b64 %0, {%1, %2};" : "=l"(r) : "f"(a), "f"(b));
    return r;
}
__device__ __forceinline__ void ffma2(unsigned long long& d,
                                      unsigned long long a, unsigned long long b) {
    asm("fma.rn.f32x2 %0, %1, %2, %3;" : "=l"(d) : "l"(a), "l"(b), "l"(d));
}
__device__ __forceinline__ void unpack2(unsigned long long v, float& lo, float& hi) {
    asm("mov.b64 {%0, %1}, %2;" : "=f"(lo), "=f"(hi) : "l"(v));
}

// ---------------------------------------------------------------------------
// K0: zero counters
// ---------------------------------------------------------------------------
__global__ void k_init() {
    int i = blockIdx.x * blockDim.x + threadIdx.x;
    if (i < NN) { g_degi[i] = 0; g_cnt[i] = 0; }
}

// ---------------------------------------------------------------------------
// K1: degree counts (row for nd, col for CSR)
// ---------------------------------------------------------------------------
__global__ void k_count(const int* __restrict__ ei) {
    int e = blockIdx.x * blockDim.x + threadIdx.x;
    if (e < EE) {
        atomicAdd(&g_degi[ei[e]], 1);
        atomicAdd(&g_cnt[ei[EE + e]], 1);
    }
}

// ---------------------------------------------------------------------------
// K2a/b/c: 3-phase exclusive scan of g_cnt -> g_off, g_cursor
// ---------------------------------------------------------------------------
__global__ void k_scan1() {
    __shared__ int wsum[8];
    const int t = threadIdx.x, lane = t & 31, wid = t >> 5;
    int i = blockIdx.x * 256 + t;
    int v = (i < NN) ? g_cnt[i] : 0;
    int s = v;
    #pragma unroll
    for (int d = 16; d; d >>= 1) s += __shfl_xor_sync(0xffffffffu, s, d);
    if (lane == 0) wsum[wid] = s;
    __syncthreads();
    if (t == 0) {
        int tot = 0;
        #pragma unroll
        for (int w = 0; w < 8; w++) tot += wsum[w];
        g_bsum[blockIdx.x] = tot;
    }
}

__global__ void k_scan2(int nblocks) {
    __shared__ int wsum[8];
    const int t = threadIdx.x, lane = t & 31, wid = t >> 5;
    int v = (t < nblocks) ? g_bsum[t] : 0;
    int x = v;
    #pragma unroll
    for (int d = 1; d < 32; d <<= 1) {
        int y = __shfl_up_sync(0xffffffffu, x, d);
        if (lane >= d) x += y;
    }
    if (lane == 31) wsum[wid] = x;
    __syncthreads();
    int woff = 0;
    #pragma unroll
    for (int w = 0; w < 8; w++) if (w < wid) woff += wsum[w];
    g_bpre[t] = woff + x - v;   // exclusive prefix of block sums
}

__global__ void k_scan3() {
    __shared__ int wsum[8];
    const int t = threadIdx.x, lane = t & 31, wid = t >> 5;
    int i = blockIdx.x * 256 + t;
    int v = (i < NN) ? g_cnt[i] : 0;
    int x = v;
    #pragma unroll
    for (int d = 1; d < 32; d <<= 1) {
        int y = __shfl_up_sync(0xffffffffu, x, d);
        if (lane >= d) x += y;
    }
    if (lane == 31) wsum[wid] = x;
    __syncthreads();
    int woff = 0;
    #pragma unroll
    for (int w = 0; w < 8; w++) if (w < wid) woff += wsum[w];
    int excl = g_bpre[blockIdx.x] + woff + x - v;
    if (i < NN) { g_off[i] = excl; g_cursor[i] = excl; }
    if (i == 0) g_off[NN] = EE;
}

// ---------------------------------------------------------------------------
// K3: per-node precompute: nd, hn = nd*h, gate projections a/bp
//     block = 256 threads, 32 nodes, smem-staged, no shuffles
// ---------------------------------------------------------------------------
__global__ __launch_bounds__(256) void k_node(const float* __restrict__ h,
                                              const float* __restrict__ gate_w) {
    __shared__ float hs[32 * 64];
    __shared__ float ws[512];
    __shared__ float nds[32];
    const int t = threadIdx.x;
    const int v0 = blockIdx.x * 32;
    const int nval = (NN - v0 < 32) ? (NN - v0) : 32;
    const int lim4 = nval * 16;   // valid float4 count

    const float4* hg = reinterpret_cast<const float4*>(h + v0 * 64);
    float4* hs4 = reinterpret_cast<float4*>(hs);
    hs4[t]       = (t < lim4)       ? hg[t]       : make_float4(0, 0, 0, 0);
    hs4[t + 256] = (t + 256 < lim4) ? hg[t + 256] : make_float4(0, 0, 0, 0);
    if (t < 128) reinterpret_cast<float4*>(ws)[t] =
        reinterpret_cast<const float4*>(gate_w)[t];
    if (t < 32) {
        float ndv = 0.0f;
        if (t < nval) {
            ndv = rsqrtf(fmaxf((float)g_degi[v0 + t], 1.0f));
            g_nd[v0 + t] = ndv;
        }
        nds[t] = ndv;
    }
    __syncthreads();

    // hn = nd * h
    float4* hng = reinterpret_cast<float4*>(g_hn + v0 * 64);
    #pragma unroll
    for (int i = 0; i < 2; i++) {
        int idx = t + i * 256;
        if (idx < lim4) {
            float s = nds[idx >> 4];
            float4 hv = hs4[idx];
            hng[idx] = make_float4(s * hv.x, s * hv.y, s * hv.z, s * hv.w);
        }
    }

    // gate dots: thread = (node v = t>>3, k = t&7), hh = k&3, part = k>>2
    const int v = t >> 3, k = t & 7, hh = k & 3, part = k >> 2;
    const float4* hv4 = reinterpret_cast<const float4*>(hs + v * 64);
    const float4* w4 = reinterpret_cast<const float4*>(ws + hh * 128 + part * 64);
    float acc = 0.0f;
    #pragma unroll
    for (int i = 0; i < 16; i++) {
        float4 a = hv4[i], b = w4[i];
        acc += a.x * b.x + a.y * b.y + a.z * b.z + a.w * b.w;
    }
    if (v < nval) {
        if (part == 0) g_a[(v0 + v) * 4 + hh] = acc;
        else           g_bp[(v0 + v) * 4 + hh] = acc;
    }
}

// ---------------------------------------------------------------------------
// K4: scatter edges into col-sorted order (store row index)
// ---------------------------------------------------------------------------
__global__ void k_scatter(const int* __restrict__ ei) {
    int e = blockIdx.x * blockDim.x + threadIdx.x;
    if (e < EE) {
        int row = ei[e];
        int col = ei[EE + e];
        int pos = atomicAdd(&g_cursor[col], 1);
        g_srow[pos] = row;
    }
}

// ---------------------------------------------------------------------------
// K5: segment reduction, 2 nodes per warp (16 lanes each), no atomics.
//     Per 4-edge batch per half: lanes compute 16 gates; each edge's hn[row]
//     gathered as one ulonglong2 (float4) per lane; FFMA2 accumulation.
// ---------------------------------------------------------------------------
__global__ __launch_bounds__(256) void k_gather(const float* __restrict__ gate_b) {
    const unsigned FULL = 0xffffffffu;
    const int t = threadIdx.x, lane = t & 31;
    const int half = lane >> 4, hl = lane & 15;
    const int n = blockIdx.x * 16 + ((t >> 5) << 1) + half;   // NN % 16 == 0

    const int beg = g_off[n], end = g_off[n + 1];
    const float ndc = g_nd[n];
    const int hh = hl & 3;
    const float bpb = g_bp[n * 4 + hh] + gate_b[hh];

    unsigned long long acc[8];
    #pragma unroll
    for (int i = 0; i < 8; i++) acc[i] = 0ULL;

    int nb = (end - beg + 3) >> 2;
    int nbo = __shfl_xor_sync(FULL, nb, 16);
    const int nbmax = (nb > nbo) ? nb : nbo;

    for (int b = 0; b < nbmax; b++) {
        const int base = beg + (b << 2);
        const int idx = base + (hl >> 2);
        const int row_l = (idx < end) ? g_srow[idx] : 0;
        const float g = tanhf(g_a[row_l * 4 + hh] + bpb);
        const int cnt = end - base;   // half-uniform; may be <= 0
        #pragma unroll
        for (int j = 0; j < 4; j++) {
            const int src = (half << 4) + (j << 2);
            const int   rj = __shfl_sync(FULL, row_l, src);
            const float g0 = __shfl_sync(FULL, g, src);
            const float g1 = __shfl_sync(FULL, g, src + 1);
            const float g2 = __shfl_sync(FULL, g, src + 2);
            const float g3 = __shfl_sync(FULL, g, src + 3);
            if (j < cnt) {
                ulonglong2 hv =
                    *reinterpret_cast<const ulonglong2*>(g_hn + rj * 64 + 4 * hl);
                unsigned long long gp;
                gp = pack2(g0, g0); ffma2(acc[0], gp, hv.x); ffma2(acc[1], gp, hv.y);
                gp = pack2(g1, g1); ffma2(acc[2], gp, hv.x); ffma2(acc[3], gp, hv.y);
                gp = pack2(g2, g2); ffma2(acc[4], gp, hv.x); ffma2(acc[5], gp, hv.y);
                gp = pack2(g3, g3); ffma2(acc[6], gp, hv.x); ffma2(acc[7], gp, hv.y);
            }
        }
    }

    float* sp = g_s + n * 256 + 4 * hl;
    #pragma unroll
    for (int h2 = 0; h2 < 4; h2++) {
        float lo0, hi0, lo1, hi1;
        unpack2(acc[h2 * 2],     lo0, hi0);
        unpack2(acc[h2 * 2 + 1], lo1, hi1);
        *reinterpret_cast<float4*>(sp + h2 * 64) =
            make_float4(ndc * lo0, ndc * hi0, ndc * lo1, ndc * hi1);
    }
}

// ---------------------------------------------------------------------------
// K6: out = relu(s @ W_cat^T + b_cat), FFMA2 inner product
//     block: 256 threads, 16 nodes; thread = (o = t&63, k-quarter = t>>6)
// ---------------------------------------------------------------------------
__global__ __launch_bounds__(256) void k_proj(const float* __restrict__ W_cat,
                                              const float* __restrict__ b_cat,
                                              float* __restrict__ out) {
    __shared__ float s_sh[16][256];
    __shared__ float red[3][16][64];
    const int t = threadIdx.x;
    const int v0 = blockIdx.x * 16;

    const float4* sg = reinterpret_cast<const float4*>(g_s + v0 * 256);
    float4* ss4 = reinterpret_cast<float4*>(&s_sh[0][0]);
    #pragma unroll
    for (int i = 0; i < 4; i++) ss4[t + i * 256] = sg[t + i * 256];
    __syncthreads();

    const int o = t & 63, qr = t >> 6;
    const ulonglong2* wg =
        reinterpret_cast<const ulonglong2*>(W_cat + o * 256 + qr * 64);
    ulonglong2 wr[16];
    #pragma unroll
    for (int i = 0; i < 16; i++) wr[i] = wg[i];

    unsigned long long accP[16];
    #pragma unroll
    for (int v = 0; v < 16; v++) accP[v] = 0ULL;

    #pragma unroll
    for (int kk = 0; kk < 16; kk++) {
        ulonglong2 w2 = wr[kk];
        #pragma unroll
        for (int v = 0; v < 16; v++) {
            ulonglong2 sv = *reinterpret_cast<const ulonglong2*>(
                &s_sh[v][qr * 64 + kk * 4]);
            ffma2(accP[v], w2.x, sv.x);
            ffma2(accP[v], w2.y, sv.y);
        }
    }

    float acc[16];
    #pragma unroll
    for (int v = 0; v < 16; v++) {
        float lo, hi;
        unpack2(accP[v], lo, hi);
        acc[v] = lo + hi;
    }

    if (qr > 0) {
        #pragma unroll
        for (int v = 0; v < 16; v++) red[qr - 1][v][o] = acc[v];
    }
    __syncthreads();
    if (qr == 0) {
        float b = b_cat[o];
        #pragma unroll
        for (int v = 0; v < 16; v++) {
            float sum = acc[v] + red[0][v][o] + red[1][v][o] + red[2][v][o] + b;
            out[(v0 + v) * 64 + o] = fmaxf(sum, 0.0f);
        }
    }
}

// ---------------------------------------------------------------------------
extern "C" void kernel_launch(void* const* d_in, const int* in_sizes, int n_in,
                              void* d_out, int out_size) {
    const float* h      = (const float*)d_in[0];
    const int*   ei     = (const int*)d_in[1];
    const float* gate_w = (const float*)d_in[2];
    const float* gate_b = (const float*)d_in[3];
    const float* W_cat  = (const float*)d_in[4];
    const float* b_cat  = (const float*)d_in[5];
    float* out = (float*)d_out;

    const int nsb = (NN + 255) / 256;   // 196 scan blocks

    k_init<<<(NN + 255) / 256, 256>>>();
    k_count<<<(EE + 255) / 256, 256>>>(ei);
    k_scan1<<<nsb, 256>>>();
    k_scan2<<<1, 256>>>(nsb);
    k_scan3<<<nsb, 256>>>();
    k_node<<<(NN + 31) / 32, 256>>>(h, gate_w);
    k_scatter<<<(EE + 255) / 256, 256>>>(ei);
    k_gather<<<NN / 16, 256>>>(gate_b);
    k_proj<<<NN / 16, 256>>>(W_cat, b_cat, out);
}

// round 8
// speedup vs baseline: 1.8025x; 1.2251x over previous
#include <cuda_runtime.h>

#define NN 50000
#define EE 800000
#define DD 64
#define HH 4
#define OUTD 64
#define NSB 196   // (NN+255)/256

// ---------------------------------------------------------------------------
// Scratch (__device__ globals: allocation-free)
// ---------------------------------------------------------------------------
__device__ int    g_degi[NN];        // out-degree over row (for nd)
__device__ int    g_cnt[NN];         // in-degree over col (for CSR)
__device__ int    g_off[NN + 1];     // CSR offsets by col
__device__ int    g_cursor[NN];      // scatter cursors
__device__ int    g_srow[EE];        // row index of edges, sorted by col
__device__ float4 g_gate4[EE];       // 4 head-gates per edge, sorted by col
__device__ float  g_nd[NN];
__device__ float  g_a[NN * HH];      // h[v] . w1_h
__device__ float  g_bp[NN * HH];     // h[v] . w2_h
__device__ float  g_hn[NN * DD];     // nd[v] * h[v]
__device__ float  g_s[NN * HH * DD]; // aggregated (pre-projection) messages
__device__ int    g_bsum[256];       // scan block sums
__device__ float4 g_wp[4096];        // repacked W_cat: wp[(kk*4+qr)*64+o]

// ---------------------------------------------------------------------------
// packed f32x2 helpers (FFMA2)
// ---------------------------------------------------------------------------
__device__ __forceinline__ unsigned long long pack2(float a, float b) {
    unsigned long long r;
    asm("mov.b64 %0, {%1, %2};" : "=l"(r) : "f"(a), "f"(b));
    return r;
}
__device__ __forceinline__ void ffma2(unsigned long long& d,
                                      unsigned long long a, unsigned long long b) {
    asm("fma.rn.f32x2 %0, %1, %2, %3;" : "=l"(d) : "l"(a), "l"(b), "l"(d));
}
__device__ __forceinline__ void unpack2(unsigned long long v, float& lo, float& hi) {
    asm("mov.b64 {%0, %1}, %2;" : "=f"(lo), "=f"(hi) : "l"(v));
}

// ---------------------------------------------------------------------------
// K0: zero counters + repack W_cat into lane-consecutive layout
// ---------------------------------------------------------------------------
__global__ void k_init(const float* __restrict__ W_cat) {
    int i = blockIdx.x * blockDim.x + threadIdx.x;
    if (i < NN) { g_degi[i] = 0; g_cnt[i] = 0; }
    if (i < 4096) {
        int o = i & 63, qr = (i >> 6) & 3, kk = i >> 8;
        g_wp[i] = *reinterpret_cast<const float4*>(W_cat + o * 256 + qr * 64 + kk * 4);
    }
}

// ---------------------------------------------------------------------------
// K1: degree counts (row for nd, col for CSR)
// ---------------------------------------------------------------------------
__global__ void k_count(const int* __restrict__ ei) {
    int e = blockIdx.x * blockDim.x + threadIdx.x;
    if (e < EE) {
        atomicAdd(&g_degi[ei[e]], 1);
        atomicAdd(&g_cnt[ei[EE + e]], 1);
    }
}

// ---------------------------------------------------------------------------
// K2a: per-256-chunk sums
// ---------------------------------------------------------------------------
__global__ void k_scan1() {
    __shared__ int wsum[8];
    const int t = threadIdx.x, lane = t & 31, wid = t >> 5;
    int i = blockIdx.x * 256 + t;
    int v = (i < NN) ? g_cnt[i] : 0;
    int s = v;
    #pragma unroll
    for (int d = 16; d; d >>= 1) s += __shfl_xor_sync(0xffffffffu, s, d);
    if (lane == 0) wsum[wid] = s;
    __syncthreads();
    if (t == 0) {
        int tot = 0;
        #pragma unroll
        for (int w = 0; w < 8; w++) tot += wsum[w];
        g_bsum[blockIdx.x] = tot;
    }
}

// ---------------------------------------------------------------------------
// K2b: merged block-prefix + intra-block exclusive scan -> g_off, g_cursor
//      (each block computes its own prefix by masked reduction of g_bsum)
// ---------------------------------------------------------------------------
__global__ void k_scan3() {
    __shared__ int wsum[8];
    __shared__ int bpre_sh;
    const int t = threadIdx.x, lane = t & 31, wid = t >> 5;

    // block prefix = sum of g_bsum[0 .. blockIdx.x)
    int bv = (t < blockIdx.x) ? g_bsum[t] : 0;   // NSB=196 <= 256
    #pragma unroll
    for (int d = 16; d; d >>= 1) bv += __shfl_xor_sync(0xffffffffu, bv, d);
    if (lane == 0) wsum[wid] = bv;
    __syncthreads();
    if (t == 0) {
        int s = 0;
        #pragma unroll
        for (int w = 0; w < 8; w++) s += wsum[w];
        bpre_sh = s;
    }
    __syncthreads();

    int i = blockIdx.x * 256 + t;
    int v = (i < NN) ? g_cnt[i] : 0;
    int x = v;
    #pragma unroll
    for (int d = 1; d < 32; d <<= 1) {
        int y = __shfl_up_sync(0xffffffffu, x, d);
        if (lane >= d) x += y;
    }
    __syncthreads();           // protect wsum reuse
    if (lane == 31) wsum[wid] = x;
    __syncthreads();
    int woff = 0;
    #pragma unroll
    for (int w = 0; w < 8; w++) if (w < wid) woff += wsum[w];
    int excl = bpre_sh + woff + x - v;
    if (i < NN) { g_off[i] = excl; g_cursor[i] = excl; }
    if (i == 0) g_off[NN] = EE;
}

// ---------------------------------------------------------------------------
// K3: per-node precompute: nd, hn = nd*h, gate projections a/bp
//     block = 256 threads, 32 nodes, smem-staged, no shuffles
// ---------------------------------------------------------------------------
__global__ __launch_bounds__(256) void k_node(const float* __restrict__ h,
                                              const float* __restrict__ gate_w) {
    __shared__ float hs[32 * 64];
    __shared__ float ws[512];
    __shared__ float nds[32];
    const int t = threadIdx.x;
    const int v0 = blockIdx.x * 32;
    const int nval = (NN - v0 < 32) ? (NN - v0) : 32;
    const int lim4 = nval * 16;   // valid float4 count

    const float4* hg = reinterpret_cast<const float4*>(h + v0 * 64);
    float4* hs4 = reinterpret_cast<float4*>(hs);
    hs4[t]       = (t < lim4)       ? hg[t]       : make_float4(0, 0, 0, 0);
    hs4[t + 256] = (t + 256 < lim4) ? hg[t + 256] : make_float4(0, 0, 0, 0);
    if (t < 128) reinterpret_cast<float4*>(ws)[t] =
        reinterpret_cast<const float4*>(gate_w)[t];
    if (t < 32) {
        float ndv = 0.0f;
        if (t < nval) {
            ndv = rsqrtf(fmaxf((float)g_degi[v0 + t], 1.0f));
            g_nd[v0 + t] = ndv;
        }
        nds[t] = ndv;
    }
    __syncthreads();

    // hn = nd * h
    float4* hng = reinterpret_cast<float4*>(g_hn + v0 * 64);
    #pragma unroll
    for (int i = 0; i < 2; i++) {
        int idx = t + i * 256;
        if (idx < lim4) {
            float s = nds[idx >> 4];
            float4 hv = hs4[idx];
            hng[idx] = make_float4(s * hv.x, s * hv.y, s * hv.z, s * hv.w);
        }
    }

    // gate dots: thread = (node v = t>>3, k = t&7), hh = k&3, part = k>>2
    const int v = t >> 3, k = t & 7, hh = k & 3, part = k >> 2;
    const float4* hv4 = reinterpret_cast<const float4*>(hs + v * 64);
    const float4* w4 = reinterpret_cast<const float4*>(ws + hh * 128 + part * 64);
    float acc = 0.0f;
    #pragma unroll
    for (int i = 0; i < 16; i++) {
        float4 a = hv4[i], b = w4[i];
        acc += a.x * b.x + a.y * b.y + a.z * b.z + a.w * b.w;
    }
    if (v < nval) {
        if (part == 0) g_a[(v0 + v) * 4 + hh] = acc;
        else           g_bp[(v0 + v) * 4 + hh] = acc;
    }
}

// ---------------------------------------------------------------------------
// K4: scatter edges into col-sorted order; precompute the 4 head gates here
//     (per-edge independent work -> high MLP hides the random a/bp gathers)
// ---------------------------------------------------------------------------
__global__ void k_scatter(const int* __restrict__ ei,
                          const float* __restrict__ gate_b) {
    int e = blockIdx.x * blockDim.x + threadIdx.x;
    if (e >= EE) return;
    int row = ei[e];
    int col = ei[EE + e];
    float4 a  = *reinterpret_cast<const float4*>(g_a + row * 4);
    float4 bp = *reinterpret_cast<const float4*>(g_bp + col * 4);
    float4 gb = *reinterpret_cast<const float4*>(gate_b);
    float4 g;
    g.x = tanhf(a.x + bp.x + gb.x);
    g.y = tanhf(a.y + bp.y + gb.y);
    g.z = tanhf(a.z + bp.z + gb.z);
    g.w = tanhf(a.w + bp.w + gb.w);
    int pos = atomicAdd(&g_cursor[col], 1);
    g_gate4[pos] = g;
    g_srow[pos] = row;
}

// ---------------------------------------------------------------------------
// K5: segment reduction, 2 nodes per warp (16 lanes each), no atomics,
//     no shuffles: per edge, broadcast-load srow + gate4, then one
//     LDG.128 of hn[row] per lane and 8 FFMA2.
// ---------------------------------------------------------------------------
__global__ __launch_bounds__(256) void k_gather() {
    const int t = threadIdx.x, lane = t & 31;
    const int half = lane >> 4, hl = lane & 15;
    const int n = blockIdx.x * 16 + ((t >> 5) << 1) + half;   // NN % 16 == 0

    const int beg = g_off[n], end = g_off[n + 1];
    const float ndc = g_nd[n];

    unsigned long long acc[8];
    #pragma unroll
    for (int i = 0; i < 8; i++) acc[i] = 0ULL;

    for (int base = beg; base < end; base += 4) {
        const int cnt = end - base;
        #pragma unroll
        for (int j = 0; j < 4; j++) {
            if (j < cnt) {
                const int rj = g_srow[base + j];
                const float4 gj = g_gate4[base + j];
                const ulonglong2 hv =
                    *reinterpret_cast<const ulonglong2*>(g_hn + rj * 64 + 4 * hl);
                unsigned long long gp;
                gp = pack2(gj.x, gj.x); ffma2(acc[0], gp, hv.x); ffma2(acc[1], gp, hv.y);
                gp = pack2(gj.y, gj.y); ffma2(acc[2], gp, hv.x); ffma2(acc[3], gp, hv.y);
                gp = pack2(gj.z, gj.z); ffma2(acc[4], gp, hv.x); ffma2(acc[5], gp, hv.y);
                gp = pack2(gj.w, gj.w); ffma2(acc[6], gp, hv.x); ffma2(acc[7], gp, hv.y);
            }
        }
    }

    float* sp = g_s + n * 256 + 4 * hl;
    #pragma unroll
    for (int h2 = 0; h2 < 4; h2++) {
        float lo0, hi0, lo1, hi1;
        unpack2(acc[h2 * 2],     lo0, hi0);
        unpack2(acc[h2 * 2 + 1], lo1, hi1);
        *reinterpret_cast<float4*>(sp + h2 * 64) =
            make_float4(ndc * lo0, ndc * hi0, ndc * lo1, ndc * hi1);
    }
}

// ---------------------------------------------------------------------------
// K6: out = relu(s @ W_cat^T + b_cat), FFMA2, repacked-W coalesced preload
//     block: 256 threads, 16 nodes; thread = (o = t&63, k-quarter = t>>6)
// ---------------------------------------------------------------------------
__global__ __launch_bounds__(256) void k_proj(const float* __restrict__ b_cat,
                                              float* __restrict__ out) {
    __shared__ float s_sh[16][256];
    __shared__ float red[3][16][64];
    const int t = threadIdx.x;
    const int v0 = blockIdx.x * 16;

    const float4* sg = reinterpret_cast<const float4*>(g_s + v0 * 256);
    float4* ss4 = reinterpret_cast<float4*>(&s_sh[0][0]);
    #pragma unroll
    for (int i = 0; i < 4; i++) ss4[t + i * 256] = sg[t + i * 256];
    __syncthreads();

    const int o = t & 63, qr = t >> 6;
    const ulonglong2* wp = reinterpret_cast<const ulonglong2*>(g_wp);
    ulonglong2 wr[16];
    #pragma unroll
    for (int kk = 0; kk < 16; kk++) wr[kk] = wp[(kk * 4 + qr) * 64 + o];

    unsigned long long accP[16];
    #pragma unroll
    for (int v = 0; v < 16; v++) accP[v] = 0ULL;

    #pragma unroll
    for (int kk = 0; kk < 16; kk++) {
        ulonglong2 w2 = wr[kk];
        #pragma unroll
        for (int v = 0; v < 16; v++) {
            ulonglong2 sv = *reinterpret_cast<const ulonglong2*>(
                &s_sh[v][qr * 64 + kk * 4]);
            ffma2(accP[v], w2.x, sv.x);
            ffma2(accP[v], w2.y, sv.y);
        }
    }

    float acc[16];
    #pragma unroll
    for (int v = 0; v < 16; v++) {
        float lo, hi;
        unpack2(accP[v], lo, hi);
        acc[v] = lo + hi;
    }

    if (qr > 0) {
        #pragma unroll
        for (int v = 0; v < 16; v++) red[qr - 1][v][o] = acc[v];
    }
    __syncthreads();
    if (qr == 0) {
        float b = b_cat[o];
        #pragma unroll
        for (int v = 0; v < 16; v++) {
            float sum = acc[v] + red[0][v][o] + red[1][v][o] + red[2][v][o] + b;
            out[(v0 + v) * 64 + o] = fmaxf(sum, 0.0f);
        }
    }
}

// ---------------------------------------------------------------------------
extern "C" void kernel_launch(void* const* d_in, const int* in_sizes, int n_in,
                              void* d_out, int out_size) {
    const float* h      = (const float*)d_in[0];
    const int*   ei     = (const int*)d_in[1];
    const float* gate_w = (const float*)d_in[2];
    const float* gate_b = (const float*)d_in[3];
    const float* W_cat  = (const float*)d_in[4];
    const float* b_cat  = (const float*)d_in[5];
    float* out = (float*)d_out;

    k_init<<<NSB, 256>>>(W_cat);
    k_count<<<(EE + 255) / 256, 256>>>(ei);
    k_scan1<<<NSB, 256>>>();
    k_scan3<<<NSB, 256>>>();
    k_node<<<(NN + 31) / 32, 256>>>(h, gate_w);
    k_scatter<<<(EE + 255) / 256, 256>>>(ei, gate_b);
    k_gather<<<NN / 16, 256>>>();
    k_proj<<<NN / 16, 256>>>(b_cat, out);
}

// round 9
// speedup vs baseline: 1.8412x; 1.0215x over previous
#include <cuda_runtime.h>

#define NN 50000
#define EE 800000
#define DD 64
#define HH 4
#define OUTD 64
#define NSB 196   // (NN+255)/256
#define NODEB ((NN + 31) / 32)   // 1563 node-phase blocks

// ---------------------------------------------------------------------------
// Scratch (__device__ globals: allocation-free, zero-initialized at load;
// k_proj re-zeroes the counters at the end of every launch so each graph
// replay starts from a clean state)
// ---------------------------------------------------------------------------
__device__ int    g_degi[NN];        // out-degree over row (for nd)
__device__ int    g_cnt[NN];         // in-degree over col (for CSR)
__device__ int    g_off[NN + 1];     // CSR offsets by col
__device__ int    g_cursor[NN];      // scatter cursors
__device__ int    g_srow[EE];        // row index of edges, sorted by col
__device__ float4 g_gate4[EE];       // 4 head-gates per edge, sorted by col
__device__ float  g_nd[NN];
__device__ float  g_a[NN * HH];      // h[v] . w1_h
__device__ float  g_bp[NN * HH];     // h[v] . w2_h
__device__ float  g_hn[NN * DD];     // nd[v] * h[v]
__device__ float  g_s[NN * HH * DD]; // aggregated (pre-projection) messages
__device__ int    g_bsum[256];       // scan block sums
__device__ float4 g_wp[4096];        // repacked W_cat: wp[(kk*4+qr)*64+o]

// ---------------------------------------------------------------------------
// packed f32x2 helpers (FFMA2)
// ---------------------------------------------------------------------------
__device__ __forceinline__ unsigned long long pack2(float a, float b) {
    unsigned long long r;
    asm("mov.b64 %0, {%1, %2};" : "=l"(r) : "f"(a), "f"(b));
    return r;
}
__device__ __forceinline__ void ffma2(unsigned long long& d,
                                      unsigned long long a, unsigned long long b) {
    asm("fma.rn.f32x2 %0, %1, %2, %3;" : "=l"(d) : "l"(a), "l"(b), "l"(d));
}
__device__ __forceinline__ void unpack2(unsigned long long v, float& lo, float& hi) {
    asm("mov.b64 {%0, %1}, %2;" : "=f"(lo), "=f"(hi) : "l"(v));
}

// fast tanh: 1 - 2/(exp(2x)+1); MUFU.EX2 + MUFU.RCP, correct at +/-inf
__device__ __forceinline__ float fast_tanh(float x) {
    float e = __expf(2.0f * x);
    return 1.0f - __fdividef(2.0f, e + 1.0f);
}

// ---------------------------------------------------------------------------
// K1: degree counts (row for nd, col for CSR) + W_cat repack (independent)
// ---------------------------------------------------------------------------
__global__ void k_count(const int* __restrict__ ei,
                        const float* __restrict__ W_cat) {
    int e = blockIdx.x * blockDim.x + threadIdx.x;
    if (e < 4096) {
        int o = e & 63, qr = (e >> 6) & 3, kk = e >> 8;
        g_wp[e] = *reinterpret_cast<const float4*>(W_cat + o * 256 + qr * 64 + kk * 4);
    }
    if (e < EE) {
        atomicAdd(&g_degi[ei[e]], 1);
        atomicAdd(&g_cnt[ei[EE + e]], 1);
    }
}

// ---------------------------------------------------------------------------
// K2a: per-256-chunk sums
// ---------------------------------------------------------------------------
__global__ void k_scan1() {
    __shared__ int wsum[8];
    const int t = threadIdx.x, lane = t & 31, wid = t >> 5;
    int i = blockIdx.x * 256 + t;
    int v = (i < NN) ? g_cnt[i] : 0;
    int s = v;
    #pragma unroll
    for (int d = 16; d; d >>= 1) s += __shfl_xor_sync(0xffffffffu, s, d);
    if (lane == 0) wsum[wid] = s;
    __syncthreads();
    if (t == 0) {
        int tot = 0;
        #pragma unroll
        for (int w = 0; w < 8; w++) tot += wsum[w];
        g_bsum[blockIdx.x] = tot;
    }
}

// ---------------------------------------------------------------------------
// K2b (fused): blocks [0, NSB) finish the exclusive scan -> g_off, g_cursor;
//              blocks [NSB, NSB+NODEB) do per-node precompute:
//              nd, hn = nd*h, gate projections a/bp.
//              Both depend only on the count phase.
// ---------------------------------------------------------------------------
__global__ __launch_bounds__(256) void k_scan_node(const float* __restrict__ h,
                                                   const float* __restrict__ gate_w) {
    const int t = threadIdx.x, lane = t & 31, wid = t >> 5;

    if (blockIdx.x < NSB) {
        // ---- scan phase ----
        __shared__ int wsum[8];
        __shared__ int bpre_sh;

        int bv = (t < blockIdx.x) ? g_bsum[t] : 0;   // NSB <= 256
        #pragma unroll
        for (int d = 16; d; d >>= 1) bv += __shfl_xor_sync(0xffffffffu, bv, d);
        if (lane == 0) wsum[wid] = bv;
        __syncthreads();
        if (t == 0) {
            int s = 0;
            #pragma unroll
            for (int w = 0; w < 8; w++) s += wsum[w];
            bpre_sh = s;
        }
        __syncthreads();

        int i = blockIdx.x * 256 + t;
        int v = (i < NN) ? g_cnt[i] : 0;
        int x = v;
        #pragma unroll
        for (int d = 1; d < 32; d <<= 1) {
            int y = __shfl_up_sync(0xffffffffu, x, d);
            if (lane >= d) x += y;
        }
        __syncthreads();           // protect wsum reuse
        if (lane == 31) wsum[wid] = x;
        __syncthreads();
        int woff = 0;
        #pragma unroll
        for (int w = 0; w < 8; w++) if (w < wid) woff += wsum[w];
        int excl = bpre_sh + woff + x - v;
        if (i < NN) { g_off[i] = excl; g_cursor[i] = excl; }
        if (i == 0) g_off[NN] = EE;
        return;
    }

    // ---- node phase ----
    __shared__ float hs[32 * 64];
    __shared__ float ws[512];
    __shared__ float nds[32];
    const int v0 = (blockIdx.x - NSB) * 32;
    const int nval = (NN - v0 < 32) ? (NN - v0) : 32;
    const int lim4 = nval * 16;   // valid float4 count

    const float4* hg = reinterpret_cast<const float4*>(h + v0 * 64);
    float4* hs4 = reinterpret_cast<float4*>(hs);
    hs4[t]       = (t < lim4)       ? hg[t]       : make_float4(0, 0, 0, 0);
    hs4[t + 256] = (t + 256 < lim4) ? hg[t + 256] : make_float4(0, 0, 0, 0);
    if (t < 128) reinterpret_cast<float4*>(ws)[t] =
        reinterpret_cast<const float4*>(gate_w)[t];
    if (t < 32) {
        float ndv = 0.0f;
        if (t < nval) {
            ndv = rsqrtf(fmaxf((float)g_degi[v0 + t], 1.0f));
            g_nd[v0 + t] = ndv;
        }
        nds[t] = ndv;
    }
    __syncthreads();

    // hn = nd * h
    float4* hng = reinterpret_cast<float4*>(g_hn + v0 * 64);
    #pragma unroll
    for (int i = 0; i < 2; i++) {
        int idx = t + i * 256;
        if (idx < lim4) {
            float s = nds[idx >> 4];
            float4 hv = hs4[idx];
            hng[idx] = make_float4(s * hv.x, s * hv.y, s * hv.z, s * hv.w);
        }
    }

    // gate dots: thread = (node v = t>>3, k = t&7), hh = k&3, part = k>>2
    const int v = t >> 3, k = t & 7, hh = k & 3, part = k >> 2;
    const float4* hv4 = reinterpret_cast<const float4*>(hs + v * 64);
    const float4* w4 = reinterpret_cast<const float4*>(ws + hh * 128 + part * 64);
    float acc = 0.0f;
    #pragma unroll
    for (int i = 0; i < 16; i++) {
        float4 a = hv4[i], b = w4[i];
        acc += a.x * b.x + a.y * b.y + a.z * b.z + a.w * b.w;
    }
    if (v < nval) {
        if (part == 0) g_a[(v0 + v) * 4 + hh] = acc;
        else           g_bp[(v0 + v) * 4 + hh] = acc;
    }
}

// ---------------------------------------------------------------------------
// K4: scatter edges into col-sorted order; gates via fast_tanh
// ---------------------------------------------------------------------------
__global__ void k_scatter(const int* __restrict__ ei,
                          const float* __restrict__ gate_b) {
    int e = blockIdx.x * blockDim.x + threadIdx.x;
    if (e >= EE) return;
    int row = ei[e];
    int col = ei[EE + e];
    float4 a  = *reinterpret_cast<const float4*>(g_a + row * 4);
    float4 bp = *reinterpret_cast<const float4*>(g_bp + col * 4);
    float4 gb = *reinterpret_cast<const float4*>(gate_b);
    float4 g;
    g.x = fast_tanh(a.x + bp.x + gb.x);
    g.y = fast_tanh(a.y + bp.y + gb.y);
    g.z = fast_tanh(a.z + bp.z + gb.z);
    g.w = fast_tanh(a.w + bp.w + gb.w);
    int pos = atomicAdd(&g_cursor[col], 1);
    g_gate4[pos] = g;
    g_srow[pos] = row;
}

// ---------------------------------------------------------------------------
// K5: segment reduction, 2 nodes per warp (16 lanes each), no atomics,
//     no shuffles: per edge, broadcast-load srow + gate4, then one
//     LDG.128 of hn[row] per lane and 8 FFMA2.
// ---------------------------------------------------------------------------
__global__ __launch_bounds__(256) void k_gather() {
    const int t = threadIdx.x, lane = t & 31;
    const int half = lane >> 4, hl = lane & 15;
    const int n = blockIdx.x * 16 + ((t >> 5) << 1) + half;   // NN % 16 == 0

    const int beg = g_off[n], end = g_off[n + 1];
    const float ndc = g_nd[n];

    unsigned long long acc[8];
    #pragma unroll
    for (int i = 0; i < 8; i++) acc[i] = 0ULL;

    for (int base = beg; base < end; base += 4) {
        const int cnt = end - base;
        #pragma unroll
        for (int j = 0; j < 4; j++) {
            if (j < cnt) {
                const int rj = g_srow[base + j];
                const float4 gj = g_gate4[base + j];
                const ulonglong2 hv =
                    *reinterpret_cast<const ulonglong2*>(g_hn + rj * 64 + 4 * hl);
                unsigned long long gp;
                gp = pack2(gj.x, gj.x); ffma2(acc[0], gp, hv.x); ffma2(acc[1], gp, hv.y);
                gp = pack2(gj.y, gj.y); ffma2(acc[2], gp, hv.x); ffma2(acc[3], gp, hv.y);
                gp = pack2(gj.z, gj.z); ffma2(acc[4], gp, hv.x); ffma2(acc[5], gp, hv.y);
                gp = pack2(gj.w, gj.w); ffma2(acc[6], gp, hv.x); ffma2(acc[7], gp, hv.y);
            }
        }
    }

    float* sp = g_s + n * 256 + 4 * hl;
    #pragma unroll
    for (int h2 = 0; h2 < 4; h2++) {
        float lo0, hi0, lo1, hi1;
        unpack2(acc[h2 * 2],     lo0, hi0);
        unpack2(acc[h2 * 2 + 1], lo1, hi1);
        *reinterpret_cast<float4*>(sp + h2 * 64) =
            make_float4(ndc * lo0, ndc * hi0, ndc * lo1, ndc * hi1);
    }
}

// ---------------------------------------------------------------------------
// K6: out = relu(s @ W_cat^T + b_cat), FFMA2, repacked-W coalesced preload.
//     Also re-zeroes the degree/count scratch for the next graph replay.
//     block: 256 threads, 16 nodes; thread = (o = t&63, k-quarter = t>>6)
// ---------------------------------------------------------------------------
__global__ __launch_bounds__(256) void k_proj(const float* __restrict__ b_cat,
                                              float* __restrict__ out) {
    __shared__ float s_sh[16][256];
    __shared__ float red[3][16][64];
    const int t = threadIdx.x;
    const int v0 = blockIdx.x * 16;

    // counter re-zero for next replay (no dependency on this launch's reads:
    // every kernel that reads g_degi/g_cnt has already completed)
    {
        int gi = blockIdx.x * 256 + t;
        if (gi < NN) { g_degi[gi] = 0; g_cnt[gi] = 0; }
    }

    const float4* sg = reinterpret_cast<const float4*>(g_s + v0 * 256);
    float4* ss4 = reinterpret_cast<float4*>(&s_sh[0][0]);
    #pragma unroll
    for (int i = 0; i < 4; i++) ss4[t + i * 256] = sg[t + i * 256];
    __syncthreads();

    const int o = t & 63, qr = t >> 6;
    const ulonglong2* wp = reinterpret_cast<const ulonglong2*>(g_wp);
    ulonglong2 wr[16];
    #pragma unroll
    for (int kk = 0; kk < 16; kk++) wr[kk] = wp[(kk * 4 + qr) * 64 + o];

    unsigned long long accP[16];
    #pragma unroll
    for (int v = 0; v < 16; v++) accP[v] = 0ULL;

    #pragma unroll
    for (int kk = 0; kk < 16; kk++) {
        ulonglong2 w2 = wr[kk];
        #pragma unroll
        for (int v = 0; v < 16; v++) {
            ulonglong2 sv = *reinterpret_cast<const ulonglong2*>(
                &s_sh[v][qr * 64 + kk * 4]);
            ffma2(accP[v], w2.x, sv.x);
            ffma2(accP[v], w2.y, sv.y);
        }
    }

    float acc[16];
    #pragma unroll
    for (int v = 0; v < 16; v++) {
        float lo, hi;
        unpack2(accP[v], lo, hi);
        acc[v] = lo + hi;
    }

    if (qr > 0) {
        #pragma unroll
        for (int v = 0; v < 16; v++) red[qr - 1][v][o] = acc[v];
    }
    __syncthreads();
    if (qr == 0) {
        float b = b_cat[o];
        #pragma unroll
        for (int v = 0; v < 16; v++) {
            float sum = acc[v] + red[0][v][o] + red[1][v][o] + red[2][v][o] + b;
            out[(v0 + v) * 64 + o] = fmaxf(sum, 0.0f);
        }
    }
}

// ---------------------------------------------------------------------------
extern "C" void kernel_launch(void* const* d_in, const int* in_sizes, int n_in,
                              void* d_out, int out_size) {
    const float* h      = (const float*)d_in[0];
    const int*   ei     = (const int*)d_in[1];
    const float* gate_w = (const float*)d_in[2];
    const float* gate_b = (const float*)d_in[3];
    const float* W_cat  = (const float*)d_in[4];
    const float* b_cat  = (const float*)d_in[5];
    float* out = (float*)d_out;

    k_count<<<(EE + 255) / 256, 256>>>(ei, W_cat);
    k_scan1<<<NSB, 256>>>();
    k_scan_node<<<NSB + NODEB, 256>>>(h, gate_w);
    k_scatter<<<(EE + 255) / 256, 256>>>(ei, gate_b);
    k_gather<<<NN / 16, 256>>>();
    k_proj<<<NN / 16, 256>>>(b_cat, out);
}